// round 14
// baseline (speedup 1.0000x reference)
#include <cuda_runtime.h>
#include <cuda_fp16.h>
#include <cstdint>

// Problem constants (Sopa_18897856102689)
#define L_ 512
#define B_ 64
#define D_ 256
#define N_ 256
#define P_ 6
#define M_ (L_ * B_)       // 32768
#define ZERO_ (-100.0f)

// Padded-packed transition columns: groups g=0..3 (plen=3..6, 64 patterns each)
// real width w = 2*plen-1 = {5,7,9,11}; padded wp = {6,8,10,12}
// E3 = 64*(6+8+10+12) = 2304 ; group bases {0, 384, 896, 1536}
#define E3_ 2304

// Asymmetric t-split for GEMM/scan overlap: [0,384) and [384,512)
#define TSPLIT_ 384
#define MBSPLIT_ (TSPLIT_ * B_ / 128)   // 192 m-tiles in chunk 0

// Scratch. x/W operands in TILE-IMAGE layout: one tile = (128 rows x 32
// halves) = 8192 contiguous bytes = one smem stage plane.
__device__ float  g_tr[(size_t)M_ * (size_t)E3_];               // 302 MB
__device__ __align__(128) __half g_xhi[(size_t)M_ * D_];        // 16.8 MB
__device__ __align__(128) __half g_xlo[(size_t)M_ * D_];
__device__ __align__(128) __half g_whi[(size_t)E3_ * D_];       // 1.18 MB
__device__ __align__(128) __half g_wlo[(size_t)E3_ * D_];
__device__ float  g_bias3[E3_];
__device__ float  g_state[B_ * N_ * 8];                         // h0..h5, s, ts

// ===========================================================================
// helpers
// ===========================================================================
__device__ __forceinline__ uint32_t smem_to_u32(const void* p) {
    uint32_t a;
    asm("{ .reg .u64 t; cvta.to.shared.u64 t, %1; cvt.u32.u64 %0, t; }"
        : "=r"(a) : "l"(p));
    return a;
}
__device__ __forceinline__ void ldsm4(uint32_t* r, uint32_t addr) {
    asm volatile("ldmatrix.sync.aligned.m8n8.x4.shared.b16 {%0,%1,%2,%3}, [%4];"
        : "=r"(r[0]), "=r"(r[1]), "=r"(r[2]), "=r"(r[3]) : "r"(addr));
}
__device__ __forceinline__ void mma16816(float* d, const uint32_t* a,
                                         uint32_t b0, uint32_t b1) {
    asm volatile(
        "mma.sync.aligned.m16n8k16.row.col.f32.f16.f16.f32 "
        "{%0,%1,%2,%3}, {%4,%5,%6,%7}, {%8,%9}, {%0,%1,%2,%3};"
        : "+f"(d[0]), "+f"(d[1]), "+f"(d[2]), "+f"(d[3])
        : "r"(a[0]), "r"(a[1]), "r"(a[2]), "r"(a[3]), "r"(b0), "r"(b1));
}
__device__ __forceinline__ uint32_t pack2(__half a, __half b) {
    __half2 t = __halves2half2(a, b);
    return *(uint32_t*)&t;
}
__device__ __forceinline__ void cpa16(uint32_t saddr, const void* gaddr) {
    asm volatile("cp.async.cg.shared.global [%0], [%1], 16;"
                 :: "r"(saddr), "l"(gaddr));
}
__device__ __forceinline__ void cpa8(uint32_t saddr, const void* gaddr) {
    asm volatile("cp.async.ca.shared.global [%0], [%1], 8;"
                 :: "r"(saddr), "l"(gaddr));
}
#define CP_COMMIT() asm volatile("cp.async.commit_group;" ::: "memory")
#define CP_WAIT(n)  asm volatile("cp.async.wait_group %0;" :: "n"(n) : "memory")

// bulk async copy global -> shared, mbarrier completion (sm_90 PTX)
__device__ __forceinline__ void bulk_g2s(uint32_t saddr, const void* gaddr,
                                         uint32_t bytes, uint32_t mbar) {
    asm volatile(
        "cp.async.bulk.shared::cluster.global.mbarrier::complete_tx::bytes "
        "[%0], [%1], %2, [%3];"
        :: "r"(saddr), "l"(gaddr), "r"(bytes), "r"(mbar) : "memory");
}
#define MBARRIER_INIT(mbar, cnt) \
    asm volatile("mbarrier.init.shared.b64 [%0], %1;" \
                 :: "r"((uint32_t)(mbar)), "r"((uint32_t)(cnt)) : "memory")
#define MBAR_EXPECT_TX(mbar, bytes) \
    asm volatile("mbarrier.arrive.expect_tx.shared.b64 _, [%0], %1;" \
                 :: "r"((uint32_t)(mbar)), "r"((uint32_t)(bytes)) : "memory")
#define MBARRIER_WAIT_PARITY(mbar, par) do {                                   \
    uint32_t _m = (uint32_t)(mbar);                                            \
    uint32_t _p = (uint32_t)(par);                                             \
    uint32_t _d;                                                               \
    asm volatile("{\n\t.reg .pred p;\n\t"                                      \
        "mbarrier.try_wait.parity.acquire.cta.shared::cta.b64 p, [%1], %2;\n\t"\
        "selp.b32 %0, 1, 0, p;\n\t}"                                           \
        : "=r"(_d) : "r"(_m), "r"(_p) : "memory");                             \
    if (!_d) {                                                                 \
        asm volatile("{\n\t.reg .pred P1;\n\t"                                 \
            "WAIT_LOOP_%=:\n\t"                                                \
            "mbarrier.try_wait.parity.acquire.cta.shared::cta.b64 P1, [%0], %1, 0x989680;\n\t" \
            "@P1 bra.uni WAIT_DONE_%=;\n\t"                                    \
            "bra.uni WAIT_LOOP_%=;\n\t"                                        \
            "WAIT_DONE_%=:\n\t}"                                               \
            :: "r"(_m), "r"(_p) : "memory");                                   \
    }                                                                          \
} while (0)

// swizzled byte offset within a 128x32-half tile image (row=64B, 16B granule)
__device__ __forceinline__ uint32_t swzc(int row, int chunk) {  // chunk 0..3
    return (uint32_t)(row * 64 + ((chunk ^ ((row >> 1) & 3)) << 4));
}

// ===========================================================================
// Convert x: fp32 -> (hi,lo) fp16 in TILE-IMAGE layout.
// ===========================================================================
__global__ __launch_bounds__(256)
void cvt_split_tiled(const float* __restrict__ src,
                     __half* __restrict__ hi_out, __half* __restrict__ lo_out) {
    const int i = blockIdx.x * 256 + threadIdx.x;
    const int m  = i >> 5;
    const int kq = i & 31;
    const float4 v0 = *(const float4*)(src + (size_t)m * D_ + kq * 8);
    const float4 v1 = *(const float4*)(src + (size_t)m * D_ + kq * 8 + 4);
    __half h0 = __float2half_rn(v0.x), h1 = __float2half_rn(v0.y);
    __half h2 = __float2half_rn(v0.z), h3 = __float2half_rn(v0.w);
    __half h4 = __float2half_rn(v1.x), h5 = __float2half_rn(v1.y);
    __half h6 = __float2half_rn(v1.z), h7 = __float2half_rn(v1.w);
    uint4 hi = { pack2(h0, h1), pack2(h2, h3), pack2(h4, h5), pack2(h6, h7) };
    uint4 lo = { pack2(__float2half_rn(v0.x - __half2float(h0)),
                       __float2half_rn(v0.y - __half2float(h1))),
                 pack2(__float2half_rn(v0.z - __half2float(h2)),
                       __float2half_rn(v0.w - __half2float(h3))),
                 pack2(__float2half_rn(v1.x - __half2float(h4)),
                       __float2half_rn(v1.y - __half2float(h5))),
                 pack2(__float2half_rn(v1.z - __half2float(h6)),
                       __float2half_rn(v1.w - __half2float(h7))) };
    const size_t off = (size_t)((m >> 7) * 8 + (kq >> 2)) * 8192
                     + swzc(m & 127, kq & 3);
    *(uint4*)((char*)hi_out + off) = hi;
    *(uint4*)((char*)lo_out + off) = lo;
}

// ===========================================================================
// Repack W into padded-packed rows (E3) in TILE-IMAGE layout + bias gather.
// ===========================================================================
__global__ __launch_bounds__(32)
void repack_w_tiled(const float* __restrict__ diags, const float* __restrict__ bias) {
    const int e3 = blockIdx.x;
    int g, base, wp;
    if (e3 < 384)       { g = 0; base = 0;    wp = 6; }
    else if (e3 < 896)  { g = 1; base = 384;  wp = 8; }
    else if (e3 < 1536) { g = 2; base = 896;  wp = 10; }
    else                { g = 3; base = 1536; wp = 12; }
    const int plen = g + 3;
    const int w = 2 * plen - 1;
    const int r0 = e3 - base;
    const int nl = r0 / wp;
    const int j = r0 - nl * wp;
    const bool real = (j < w);
    const int n = (g << 6) + nl;
    const int e_orig = n * 12 + (j < plen ? j : 6 + (j - plen));

    const int t = threadIdx.x;                      // 0..31 (8-half chunks)
    uint4 hi = {0, 0, 0, 0}, lo = {0, 0, 0, 0};
    if (real) {
        const float4 v0 = *(const float4*)(diags + (size_t)e_orig * D_ + t * 8);
        const float4 v1 = *(const float4*)(diags + (size_t)e_orig * D_ + t * 8 + 4);
        __half h0 = __float2half_rn(v0.x), h1 = __float2half_rn(v0.y);
        __half h2 = __float2half_rn(v0.z), h3 = __float2half_rn(v0.w);
        __half h4 = __float2half_rn(v1.x), h5 = __float2half_rn(v1.y);
        __half h6 = __float2half_rn(v1.z), h7 = __float2half_rn(v1.w);
        hi = make_uint4(pack2(h0, h1), pack2(h2, h3), pack2(h4, h5), pack2(h6, h7));
        lo = make_uint4(pack2(__float2half_rn(v0.x - __half2float(h0)),
                              __float2half_rn(v0.y - __half2float(h1))),
                        pack2(__float2half_rn(v0.z - __half2float(h2)),
                              __float2half_rn(v0.w - __half2float(h3))),
                        pack2(__float2half_rn(v1.x - __half2float(h4)),
                              __float2half_rn(v1.y - __half2float(h5))),
                        pack2(__float2half_rn(v1.z - __half2float(h6)),
                              __float2half_rn(v1.w - __half2float(h7))));
    }
    const size_t off = (size_t)((e3 >> 7) * 8 + (t >> 2)) * 8192
                     + swzc(e3 & 127, t & 3);
    *(uint4*)((char*)g_whi + off) = hi;
    *(uint4*)((char*)g_wlo + off) = lo;
    if (t == 0) g_bias3[e3] = real ? bias[e_orig] : 0.0f;
}

// ===========================================================================
// GEMM (m-tile range): C[m][e3] = sum_k x[m][k]*Wpad[e3][k] + bias3[e3]
// fp16 hi/lo 3-term mma.sync; bulk staging; coalesced smem epilogue.
// At the dense-HMMA issue floor — do not touch the mainloop.
// ===========================================================================
#define NCHUNK_ 8
#define NSTAGE_ 4
#define ST_AHI 0
#define ST_ALO 8192
#define ST_BHI 16384
#define ST_BLO 24576
#define STAGE_SZ 32768
#define OFF_MBAR  512
#define OFF_TILES 1024
#define SMEM_BYTES (OFF_TILES + NSTAGE_ * STAGE_SZ)   // 132096
#define EPS_ 136   // epilogue smem row stride (floats)

__device__ __forceinline__ void gemm_issue_bulk(uint32_t sb, int slot,
                                                int chunk, int mb, int nb) {
    const uint32_t stg = sb + OFF_TILES + slot * STAGE_SZ;
    const uint32_t mbar = sb + OFF_MBAR + slot * 8;
    MBAR_EXPECT_TX(mbar, 4 * 8192);
    const size_t at = (size_t)(mb * 8 + chunk) * 8192;
    const size_t bt = (size_t)(nb * 8 + chunk) * 8192;
    bulk_g2s(stg + ST_AHI, (const char*)g_xhi + at, 8192, mbar);
    bulk_g2s(stg + ST_ALO, (const char*)g_xlo + at, 8192, mbar);
    bulk_g2s(stg + ST_BHI, (const char*)g_whi + bt, 8192, mbar);
    bulk_g2s(stg + ST_BLO, (const char*)g_wlo + bt, 8192, mbar);
}

__global__ __launch_bounds__(512, 1)
void sopa_gemm_mma(int mb0) {
    extern __shared__ char smem[];
    const uint32_t sb = smem_to_u32(smem);
    const int tid  = threadIdx.x;
    const int lane = tid & 31;
    const int warp = tid >> 5;
    const int wm = (warp >> 2) * 32;
    const int wn = (warp & 3) * 32;

    const int nb = blockIdx.x;          // e3 block (0..17)
    const int mb = mb0 + blockIdx.y;    // m block
    const int bn = nb * 128;
    const int bm = mb * 128;

    if (tid == 0) {
        #pragma unroll
        for (int s = 0; s < NSTAGE_; s++)
            MBARRIER_INIT(sb + OFF_MBAR + s * 8, 1);
    }
    __syncthreads();

    if (tid == 0) {
        #pragma unroll
        for (int s = 0; s < NSTAGE_ - 1; s++)
            gemm_issue_bulk(sb, s, s, mb, nb);
    }

    float acc[2][4][4];
    #pragma unroll
    for (int i = 0; i < 2; i++)
        #pragma unroll
        for (int j = 0; j < 4; j++)
            #pragma unroll
            for (int k = 0; k < 4; k++) acc[i][j][k] = 0.0f;

    const int lrow = lane & 15;
    const int lsel = lane >> 4;

    #pragma unroll
    for (int c = 0; c < NCHUNK_; c++) {
        MBARRIER_WAIT_PARITY(sb + OFF_MBAR + (c & 3) * 8, (c >> 2) & 1);
        __syncthreads();
        if (tid == 0 && c + NSTAGE_ - 1 < NCHUNK_)
            gemm_issue_bulk(sb, (c + NSTAGE_ - 1) & 3, c + NSTAGE_ - 1, mb, nb);

        const uint32_t st = sb + OFF_TILES + (c & 3) * STAGE_SZ;
        #pragma unroll
        for (int kk = 0; kk < 2; kk++) {
            const int chunk = kk * 2 + lsel;
            uint32_t aHi[2][4], aLo[2][4], bHi[2][4], bLo[2][4];
            #pragma unroll
            for (int mt = 0; mt < 2; mt++) {
                const uint32_t off = swzc(wm + mt * 16 + lrow, chunk);
                ldsm4(aHi[mt], st + ST_AHI + off);
                ldsm4(aLo[mt], st + ST_ALO + off);
            }
            #pragma unroll
            for (int ng = 0; ng < 2; ng++) {
                const uint32_t off = swzc(wn + ng * 16 + lrow, chunk);
                ldsm4(bHi[ng], st + ST_BHI + off);
                ldsm4(bLo[ng], st + ST_BLO + off);
            }
            #pragma unroll
            for (int mt = 0; mt < 2; mt++)
                #pragma unroll
                for (int nt = 0; nt < 4; nt++) {
                    const int ng = nt >> 1, sl = nt & 1;
                    mma16816(acc[mt][nt], aHi[mt], bHi[ng][sl], bHi[ng][sl + 2]);
                    mma16816(acc[mt][nt], aHi[mt], bLo[ng][sl], bLo[ng][sl + 2]);
                    mma16816(acc[mt][nt], aLo[mt], bHi[ng][sl], bHi[ng][sl + 2]);
                }
        }
    }

    // ---- epilogue: acc -> padded smem -> fully coalesced float4 stores ----
    __syncthreads();
    float* ebuf = (float*)(smem + OFF_TILES);
    #pragma unroll
    for (int mt = 0; mt < 2; mt++) {
        const int row = wm + mt * 16 + (lane >> 2);
        #pragma unroll
        for (int nt = 0; nt < 4; nt++) {
            const int col = wn + nt * 8 + (lane & 3) * 2;
            ebuf[row * EPS_ + col]           = acc[mt][nt][0];
            ebuf[row * EPS_ + col + 1]       = acc[mt][nt][1];
            ebuf[(row + 8) * EPS_ + col]     = acc[mt][nt][2];
            ebuf[(row + 8) * EPS_ + col + 1] = acc[mt][nt][3];
        }
    }
    __syncthreads();
    #pragma unroll
    for (int i = 0; i < 8; i++) {
        const int id  = tid + i * 512;      // 0..4095
        const int row = id >> 5;            // 0..127
        const int c4  = id & 31;            // float4 index in 128-col row
        float4 v = *(const float4*)&ebuf[row * EPS_ + c4 * 4];
        const float4 bb = *(const float4*)(g_bias3 + bn + c4 * 4);
        v.x += bb.x; v.y += bb.y; v.z += bb.z; v.w += bb.w;
        *(float4*)(g_tr + (size_t)(bm + row) * E3_ + bn + c4 * 4) = v;
    }
}

// ===========================================================================
// Scan (t range [t0, t0+tlen)): 128 blocks x 128 threads; state in g_state.
// ===========================================================================
#define SNS_ 16
#define SSTG_ 6144                       // 128 threads * 48 B
#define SCAN_SMEM (SNS_ * SSTG_)         // 98304

template<int PLEN, int WPF>
__device__ __forceinline__ void scan_body(int b, int n, int colbase,
                                          int t0, int tlen,
                                          const int* __restrict__ input_len,
                                          const float* __restrict__ epsilon,
                                          float* __restrict__ out,
                                          char* ssm, uint32_t sb, int tidx) {
    float eps[PLEN - 1];
    #pragma unroll
    for (int i = 0; i < PLEN - 1; i++) eps[i] = epsilon[n * 5 + i];

    const int len = input_len[b];
    float* st = g_state + ((size_t)b * N_ + n) * 8;

    float h[PLEN];
    float s, ts;
    if (t0 == 0) {
        h[0] = 0.0f;
        #pragma unroll
        for (int i = 1; i < PLEN; i++) h[i] = ZERO_;
        s = ZERO_;
        ts = -1.0f;                     // tanhf(-100) == -1
    } else {
        #pragma unroll
        for (int i = 0; i < PLEN; i++) h[i] = st[i];
        s = st[6];
        ts = st[7];
    }

    const float* base = g_tr + ((size_t)t0 * B_ + b) * E3_ + colbase;
    float* ob = out + ((size_t)t0 * B_ + b) * N_ + n;
    const size_t tstride = (size_t)B_ * E3_;
    const size_t ostride = (size_t)B_ * N_;
    const uint32_t slot = sb + tidx * 48;

    #pragma unroll
    for (int t = 0; t < SNS_ - 1; t++) {
        const float* g = base + (size_t)t * tstride;
        const uint32_t d = slot + t * SSTG_;
        if constexpr (WPF % 4 == 0) {
            #pragma unroll
            for (int q = 0; q < WPF / 4; q++) cpa16(d + q * 16, g + q * 4);
        } else {
            #pragma unroll
            for (int q = 0; q < WPF / 2; q++) cpa8(d + q * 8, g + q * 2);
        }
        CP_COMMIT();
    }

    #pragma unroll 4
    for (int t = 0; t < tlen; t++) {
        CP_WAIT(SNS_ - 2);
        const uint32_t doff = (uint32_t)(tidx * 48) + (t & (SNS_ - 1)) * SSTG_;
        float q[2 * PLEN - 1];
        #pragma unroll
        for (int i = 0; i < 2 * PLEN - 1; i++)
            q[i] = *(const float*)(ssm + doff + i * 4);
        if (t + SNS_ - 1 < tlen) {
            const float* g = base + (size_t)(t + SNS_ - 1) * tstride;
            const uint32_t nd = slot + ((t + SNS_ - 1) & (SNS_ - 1)) * SSTG_;
            if constexpr (WPF % 4 == 0) {
                #pragma unroll
                for (int qq = 0; qq < WPF / 4; qq++) cpa16(nd + qq * 16, g + qq * 4);
            } else {
                #pragma unroll
                for (int qq = 0; qq < WPF / 2; qq++) cpa8(nd + qq * 8, g + qq * 2);
            }
        }
        CP_COMMIT();

        float ae[PLEN];
        ae[0] = h[0];
        #pragma unroll
        for (int i = 1; i < PLEN; i++) ae[i] = fmaxf(h[i], h[i - 1] + eps[i - 1]);

        h[0] = fmaxf(0.0f, ae[0] + q[0]);
        #pragma unroll
        for (int i = 1; i < PLEN; i++)
            h[i] = fmaxf(ae[i - 1] + q[PLEN + i - 1], ae[i] + q[i]);

        float ev = h[PLEN - 1];
        if (len >= t0 + t && ev > s) {
            s = ev;
            ts = tanhf(s);
        }
        ob[(size_t)t * ostride] = ts;
    }

    // persist state for the next chunk
    #pragma unroll
    for (int i = 0; i < PLEN; i++) st[i] = h[i];
    st[6] = s;
    st[7] = ts;
}

__global__ __launch_bounds__(128)
void sopa_scan(int t0, int tlen,
               const int* __restrict__ input_len,
               const float* __restrict__ epsilon,
               float* __restrict__ out) {
    extern __shared__ char ssm[];
    const uint32_t sb = smem_to_u32(ssm);
    const int tidx = threadIdx.x;
    const int b    = blockIdx.x >> 1;
    const int half = blockIdx.x & 1;
    const int sub  = tidx >> 6;         // 0 or 1 within the half
    const int ln   = tidx & 63;         // pattern index within group
    const int g    = half * 2 + sub;    // group 0..3
    const int n    = (g << 6) | ln;

    switch (g) {
        case 0: scan_body<3, 6>(b, n, 0    + ln * 6,  t0, tlen, input_len, epsilon, out, ssm, sb, tidx); break;
        case 1: scan_body<4, 8>(b, n, 384  + ln * 8,  t0, tlen, input_len, epsilon, out, ssm, sb, tidx); break;
        case 2: scan_body<5, 10>(b, n, 896  + ln * 10, t0, tlen, input_len, epsilon, out, ssm, sb, tidx); break;
        default: scan_body<6, 12>(b, n, 1536 + ln * 12, t0, tlen, input_len, epsilon, out, ssm, sb, tidx); break;
    }
}

// ===========================================================================
extern "C" void kernel_launch(void* const* d_in, const int* in_sizes, int n_in,
                              void* d_out, int out_size) {
    const float* x         = (const float*)d_in[0];   // (L,B,D) f32
    const int*   input_len = (const int*)  d_in[1];   // (B,)   i32
    const float* diags     = (const float*)d_in[2];   // (E,D)  f32
    const float* bias      = (const float*)d_in[3];   // (E,1)  f32
    const float* epsilon   = (const float*)d_in[4];   // (N,P-1) f32
    float*       out       = (float*)d_out;           // (L,B,N) f32

    static cudaStream_t s_scan = nullptr;
    static cudaEvent_t evG0, evG1, evJoin;
    if (s_scan == nullptr) {
        cudaStreamCreateWithFlags(&s_scan, cudaStreamNonBlocking);
        cudaEventCreateWithFlags(&evG0, cudaEventDisableTiming);
        cudaEventCreateWithFlags(&evG1, cudaEventDisableTiming);
        cudaEventCreateWithFlags(&evJoin, cudaEventDisableTiming);
        cudaFuncSetAttribute(sopa_gemm_mma, cudaFuncAttributeMaxDynamicSharedMemorySize,
                             SMEM_BYTES);
        cudaFuncSetAttribute(sopa_scan, cudaFuncAttributeMaxDynamicSharedMemorySize,
                             SCAN_SMEM);
    }

    __half *xhi, *xlo;
    cudaGetSymbolAddress((void**)&xhi, g_xhi);
    cudaGetSymbolAddress((void**)&xlo, g_xlo);

    // preprocessing on the main (capture) stream
    cvt_split_tiled<<<M_ * 32 / 256, 256>>>(x, xhi, xlo);   // 4096 blocks
    repack_w_tiled<<<E3_, 32>>>(diags, bias);

    // asymmetric split: GEMM c0 = t [0,384) (192 m-tiles), c1 = t [384,512)
    {
        dim3 g0(E3_ / 128, MBSPLIT_);            // (18, 192)
        sopa_gemm_mma<<<g0, 512, SMEM_BYTES>>>(0);
        cudaEventRecord(evG0, 0);
        dim3 g1(E3_ / 128, (M_ / 128) - MBSPLIT_); // (18, 64)
        sopa_gemm_mma<<<g1, 512, SMEM_BYTES>>>(MBSPLIT_);
        cudaEventRecord(evG1, 0);
    }
    // scan c0 overlaps GEMM c1; scan c1 exposed (small)
    cudaStreamWaitEvent(s_scan, evG0, 0);
    sopa_scan<<<128, 128, SCAN_SMEM, s_scan>>>(0, TSPLIT_, input_len, epsilon, out);
    cudaStreamWaitEvent(s_scan, evG1, 0);
    sopa_scan<<<128, 128, SCAN_SMEM, s_scan>>>(TSPLIT_, L_ - TSPLIT_, input_len, epsilon, out);
    cudaEventRecord(evJoin, s_scan);
    cudaStreamWaitEvent(0, evJoin, 0);
}

// round 16
// speedup vs baseline: 1.1026x; 1.1026x over previous
#include <cuda_runtime.h>
#include <cuda_fp16.h>
#include <cstdint>

// Problem constants (Sopa_18897856102689)
#define L_ 512
#define B_ 64
#define D_ 256
#define N_ 256
#define P_ 6
#define M_ (L_ * B_)       // 32768
#define ZERO_ (-100.0f)

// Padded-packed transition columns: groups g=0..3 (plen=3..6, 64 patterns each)
// real width w = 2*plen-1 = {5,7,9,11}; padded wp = {6,8,10,12}
// E3 = 64*(6+8+10+12) = 2304 ; group bases {0, 384, 896, 1536}
#define E3_ 2304

// Scratch. x/W operands in TILE-IMAGE layout: one tile = (128 rows x 32
// halves) = 8192 contiguous bytes = one smem stage plane.
__device__ float  g_tr[(size_t)M_ * (size_t)E3_];               // 302 MB
__device__ __align__(128) __half g_xhi[(size_t)M_ * D_];        // 16.8 MB
__device__ __align__(128) __half g_xlo[(size_t)M_ * D_];
__device__ __align__(128) __half g_whi[(size_t)E3_ * D_];       // 1.18 MB
__device__ __align__(128) __half g_wlo[(size_t)E3_ * D_];
__device__ float  g_bias3[E3_];

// ===========================================================================
// helpers
// ===========================================================================
__device__ __forceinline__ uint32_t smem_to_u32(const void* p) {
    uint32_t a;
    asm("{ .reg .u64 t; cvta.to.shared.u64 t, %1; cvt.u32.u64 %0, t; }"
        : "=r"(a) : "l"(p));
    return a;
}
__device__ __forceinline__ void ldsm4(uint32_t* r, uint32_t addr) {
    asm volatile("ldmatrix.sync.aligned.m8n8.x4.shared.b16 {%0,%1,%2,%3}, [%4];"
        : "=r"(r[0]), "=r"(r[1]), "=r"(r[2]), "=r"(r[3]) : "r"(addr));
}
// fp32-accumulate HMMA (main term)
__device__ __forceinline__ void mma16816(float* d, const uint32_t* a,
                                         uint32_t b0, uint32_t b1) {
    asm volatile(
        "mma.sync.aligned.m16n8k16.row.col.f32.f16.f16.f32 "
        "{%0,%1,%2,%3}, {%4,%5,%6,%7}, {%8,%9}, {%0,%1,%2,%3};"
        : "+f"(d[0]), "+f"(d[1]), "+f"(d[2]), "+f"(d[3])
        : "r"(a[0]), "r"(a[1]), "r"(a[2]), "r"(a[3]), "r"(b0), "r"(b1));
}
// fp16-accumulate HMMA (small correction terms; possibly 2x rate)
__device__ __forceinline__ void mma16816h(uint32_t* d, const uint32_t* a,
                                          uint32_t b0, uint32_t b1) {
    asm volatile(
        "mma.sync.aligned.m16n8k16.row.col.f16.f16.f16.f16 "
        "{%0,%1}, {%2,%3,%4,%5}, {%6,%7}, {%0,%1};"
        : "+r"(d[0]), "+r"(d[1])
        : "r"(a[0]), "r"(a[1]), "r"(a[2]), "r"(a[3]), "r"(b0), "r"(b1));
}
__device__ __forceinline__ uint32_t pack2(__half a, __half b) {
    __half2 t = __halves2half2(a, b);
    return *(uint32_t*)&t;
}
__device__ __forceinline__ void cpa16(uint32_t saddr, const void* gaddr) {
    asm volatile("cp.async.cg.shared.global [%0], [%1], 16;"
                 :: "r"(saddr), "l"(gaddr));
}
__device__ __forceinline__ void cpa8(uint32_t saddr, const void* gaddr) {
    asm volatile("cp.async.ca.shared.global [%0], [%1], 8;"
                 :: "r"(saddr), "l"(gaddr));
}
#define CP_COMMIT() asm volatile("cp.async.commit_group;" ::: "memory")
#define CP_WAIT(n)  asm volatile("cp.async.wait_group %0;" :: "n"(n) : "memory")

// bulk async copy global -> shared, mbarrier completion (sm_90 PTX)
__device__ __forceinline__ void bulk_g2s(uint32_t saddr, const void* gaddr,
                                         uint32_t bytes, uint32_t mbar) {
    asm volatile(
        "cp.async.bulk.shared::cluster.global.mbarrier::complete_tx::bytes "
        "[%0], [%1], %2, [%3];"
        :: "r"(saddr), "l"(gaddr), "r"(bytes), "r"(mbar) : "memory");
}
#define MBARRIER_INIT(mbar, cnt) \
    asm volatile("mbarrier.init.shared.b64 [%0], %1;" \
                 :: "r"((uint32_t)(mbar)), "r"((uint32_t)(cnt)) : "memory")
#define MBAR_EXPECT_TX(mbar, bytes) \
    asm volatile("mbarrier.arrive.expect_tx.shared.b64 _, [%0], %1;" \
                 :: "r"((uint32_t)(mbar)), "r"((uint32_t)(bytes)) : "memory")
#define MBARRIER_WAIT_PARITY(mbar, par) do {                                   \
    uint32_t _m = (uint32_t)(mbar);                                            \
    uint32_t _p = (uint32_t)(par);                                             \
    uint32_t _d;                                                               \
    asm volatile("{\n\t.reg .pred p;\n\t"                                      \
        "mbarrier.try_wait.parity.acquire.cta.shared::cta.b64 p, [%1], %2;\n\t"\
        "selp.b32 %0, 1, 0, p;\n\t}"                                           \
        : "=r"(_d) : "r"(_m), "r"(_p) : "memory");                             \
    if (!_d) {                                                                 \
        asm volatile("{\n\t.reg .pred P1;\n\t"                                 \
            "WAIT_LOOP_%=:\n\t"                                                \
            "mbarrier.try_wait.parity.acquire.cta.shared::cta.b64 P1, [%0], %1, 0x989680;\n\t" \
            "@P1 bra.uni WAIT_DONE_%=;\n\t"                                    \
            "bra.uni WAIT_LOOP_%=;\n\t"                                        \
            "WAIT_DONE_%=:\n\t}"                                               \
            :: "r"(_m), "r"(_p) : "memory");                                   \
    }                                                                          \
} while (0)

// swizzled byte offset within a 128x32-half tile image (row=64B, 16B granule)
__device__ __forceinline__ uint32_t swzc(int row, int chunk) {  // chunk 0..3
    return (uint32_t)(row * 64 + ((chunk ^ ((row >> 1) & 3)) << 4));
}

// ===========================================================================
// Convert x: fp32 -> (hi,lo) fp16 in TILE-IMAGE layout.
// ===========================================================================
__global__ __launch_bounds__(256)
void cvt_split_tiled(const float* __restrict__ src,
                     __half* __restrict__ hi_out, __half* __restrict__ lo_out) {
    const int i = blockIdx.x * 256 + threadIdx.x;
    const int m  = i >> 5;
    const int kq = i & 31;
    const float4 v0 = *(const float4*)(src + (size_t)m * D_ + kq * 8);
    const float4 v1 = *(const float4*)(src + (size_t)m * D_ + kq * 8 + 4);
    __half h0 = __float2half_rn(v0.x), h1 = __float2half_rn(v0.y);
    __half h2 = __float2half_rn(v0.z), h3 = __float2half_rn(v0.w);
    __half h4 = __float2half_rn(v1.x), h5 = __float2half_rn(v1.y);
    __half h6 = __float2half_rn(v1.z), h7 = __float2half_rn(v1.w);
    uint4 hi = { pack2(h0, h1), pack2(h2, h3), pack2(h4, h5), pack2(h6, h7) };
    uint4 lo = { pack2(__float2half_rn(v0.x - __half2float(h0)),
                       __float2half_rn(v0.y - __half2float(h1))),
                 pack2(__float2half_rn(v0.z - __half2float(h2)),
                       __float2half_rn(v0.w - __half2float(h3))),
                 pack2(__float2half_rn(v1.x - __half2float(h4)),
                       __float2half_rn(v1.y - __half2float(h5))),
                 pack2(__float2half_rn(v1.z - __half2float(h6)),
                       __float2half_rn(v1.w - __half2float(h7))) };
    const size_t off = (size_t)((m >> 7) * 8 + (kq >> 2)) * 8192
                     + swzc(m & 127, kq & 3);
    *(uint4*)((char*)hi_out + off) = hi;
    *(uint4*)((char*)lo_out + off) = lo;
}

// ===========================================================================
// Repack W into padded-packed rows (E3) in TILE-IMAGE layout + bias gather.
// ===========================================================================
__global__ __launch_bounds__(32)
void repack_w_tiled(const float* __restrict__ diags, const float* __restrict__ bias) {
    const int e3 = blockIdx.x;
    int g, base, wp;
    if (e3 < 384)       { g = 0; base = 0;    wp = 6; }
    else if (e3 < 896)  { g = 1; base = 384;  wp = 8; }
    else if (e3 < 1536) { g = 2; base = 896;  wp = 10; }
    else                { g = 3; base = 1536; wp = 12; }
    const int plen = g + 3;
    const int w = 2 * plen - 1;
    const int r0 = e3 - base;
    const int nl = r0 / wp;
    const int j = r0 - nl * wp;
    const bool real = (j < w);
    const int n = (g << 6) + nl;
    const int e_orig = n * 12 + (j < plen ? j : 6 + (j - plen));

    const int t = threadIdx.x;                      // 0..31 (8-half chunks)
    uint4 hi = {0, 0, 0, 0}, lo = {0, 0, 0, 0};
    if (real) {
        const float4 v0 = *(const float4*)(diags + (size_t)e_orig * D_ + t * 8);
        const float4 v1 = *(const float4*)(diags + (size_t)e_orig * D_ + t * 8 + 4);
        __half h0 = __float2half_rn(v0.x), h1 = __float2half_rn(v0.y);
        __half h2 = __float2half_rn(v0.z), h3 = __float2half_rn(v0.w);
        __half h4 = __float2half_rn(v1.x), h5 = __float2half_rn(v1.y);
        __half h6 = __float2half_rn(v1.z), h7 = __float2half_rn(v1.w);
        hi = make_uint4(pack2(h0, h1), pack2(h2, h3), pack2(h4, h5), pack2(h6, h7));
        lo = make_uint4(pack2(__float2half_rn(v0.x - __half2float(h0)),
                              __float2half_rn(v0.y - __half2float(h1))),
                        pack2(__float2half_rn(v0.z - __half2float(h2)),
                              __float2half_rn(v0.w - __half2float(h3))),
                        pack2(__float2half_rn(v1.x - __half2float(h4)),
                              __float2half_rn(v1.y - __half2float(h5))),
                        pack2(__float2half_rn(v1.z - __half2float(h6)),
                              __float2half_rn(v1.w - __half2float(h7))));
    }
    const size_t off = (size_t)((e3 >> 7) * 8 + (t >> 2)) * 8192
                     + swzc(e3 & 127, t & 3);
    *(uint4*)((char*)g_whi + off) = hi;
    *(uint4*)((char*)g_wlo + off) = lo;
    if (t == 0) g_bias3[e3] = real ? bias[e_orig] : 0.0f;
}

// ===========================================================================
// GEMM: C[m][e3] = sum_k x[m][k]*Wpad[e3][k] + bias3[e3]
// hi*hi in fp32-acc MMA; hi*lo + lo*hi in fp16-acc MMA (small corrections,
// merged into fp32 at epilogue). Bulk staging; coalesced smem epilogue.
// BM=128, BN=128, BK=32, 512 threads, warp grid 4x4, warp tile 32x32.
// ===========================================================================
#define NCHUNK_ 8
#define NSTAGE_ 4
#define ST_AHI 0
#define ST_ALO 8192
#define ST_BHI 16384
#define ST_BLO 24576
#define STAGE_SZ 32768
#define OFF_MBAR  512
#define OFF_TILES 1024
#define SMEM_BYTES (OFF_TILES + NSTAGE_ * STAGE_SZ)   // 132096
#define EPS_ 136   // epilogue smem row stride (floats)

__device__ __forceinline__ void gemm_issue_bulk(uint32_t sb, int slot,
                                                int chunk, int mb, int nb) {
    const uint32_t stg = sb + OFF_TILES + slot * STAGE_SZ;
    const uint32_t mbar = sb + OFF_MBAR + slot * 8;
    MBAR_EXPECT_TX(mbar, 4 * 8192);
    const size_t at = (size_t)(mb * 8 + chunk) * 8192;
    const size_t bt = (size_t)(nb * 8 + chunk) * 8192;
    bulk_g2s(stg + ST_AHI, (const char*)g_xhi + at, 8192, mbar);
    bulk_g2s(stg + ST_ALO, (const char*)g_xlo + at, 8192, mbar);
    bulk_g2s(stg + ST_BHI, (const char*)g_whi + bt, 8192, mbar);
    bulk_g2s(stg + ST_BLO, (const char*)g_wlo + bt, 8192, mbar);
}

__global__ __launch_bounds__(512, 1)
void sopa_gemm_mma() {
    extern __shared__ char smem[];
    const uint32_t sb = smem_to_u32(smem);
    const int tid  = threadIdx.x;
    const int lane = tid & 31;
    const int warp = tid >> 5;
    const int wm = (warp >> 2) * 32;
    const int wn = (warp & 3) * 32;

    const int nb = blockIdx.x;          // e3 block (0..17)
    const int mb = blockIdx.y;          // m block (0..255)
    const int bn = nb * 128;
    const int bm = mb * 128;

    if (tid == 0) {
        #pragma unroll
        for (int s = 0; s < NSTAGE_; s++)
            MBARRIER_INIT(sb + OFF_MBAR + s * 8, 1);
    }
    __syncthreads();

    if (tid == 0) {
        #pragma unroll
        for (int s = 0; s < NSTAGE_ - 1; s++)
            gemm_issue_bulk(sb, s, s, mb, nb);
    }

    float acc[2][4][4];
    uint32_t accC[2][4][2];             // fp16 correction accumulators (half2 x2)
    #pragma unroll
    for (int i = 0; i < 2; i++)
        #pragma unroll
        for (int j = 0; j < 4; j++) {
            #pragma unroll
            for (int k = 0; k < 4; k++) acc[i][j][k] = 0.0f;
            accC[i][j][0] = 0u;
            accC[i][j][1] = 0u;
        }

    const int lrow = lane & 15;
    const int lsel = lane >> 4;

    #pragma unroll
    for (int c = 0; c < NCHUNK_; c++) {
        MBARRIER_WAIT_PARITY(sb + OFF_MBAR + (c & 3) * 8, (c >> 2) & 1);
        __syncthreads();
        if (tid == 0 && c + NSTAGE_ - 1 < NCHUNK_)
            gemm_issue_bulk(sb, (c + NSTAGE_ - 1) & 3, c + NSTAGE_ - 1, mb, nb);

        const uint32_t st = sb + OFF_TILES + (c & 3) * STAGE_SZ;
        #pragma unroll
        for (int kk = 0; kk < 2; kk++) {
            const int chunk = kk * 2 + lsel;
            uint32_t aHi[2][4], aLo[2][4], bHi[2][4], bLo[2][4];
            #pragma unroll
            for (int mt = 0; mt < 2; mt++) {
                const uint32_t off = swzc(wm + mt * 16 + lrow, chunk);
                ldsm4(aHi[mt], st + ST_AHI + off);
                ldsm4(aLo[mt], st + ST_ALO + off);
            }
            #pragma unroll
            for (int ng = 0; ng < 2; ng++) {
                const uint32_t off = swzc(wn + ng * 16 + lrow, chunk);
                ldsm4(bHi[ng], st + ST_BHI + off);
                ldsm4(bLo[ng], st + ST_BLO + off);
            }
            #pragma unroll
            for (int mt = 0; mt < 2; mt++)
                #pragma unroll
                for (int nt = 0; nt < 4; nt++) {
                    const int ng = nt >> 1, sl = nt & 1;
                    mma16816(acc[mt][nt], aHi[mt], bHi[ng][sl], bHi[ng][sl + 2]);
                    mma16816h(accC[mt][nt], aHi[mt], bLo[ng][sl], bLo[ng][sl + 2]);
                    mma16816h(accC[mt][nt], aLo[mt], bHi[ng][sl], bHi[ng][sl + 2]);
                }
        }
    }

    // merge fp16 corrections into fp32 accumulators
    #pragma unroll
    for (int mt = 0; mt < 2; mt++)
        #pragma unroll
        for (int nt = 0; nt < 4; nt++) {
            float2 c01 = __half22float2(*(__half2*)&accC[mt][nt][0]);
            float2 c23 = __half22float2(*(__half2*)&accC[mt][nt][1]);
            acc[mt][nt][0] += c01.x;
            acc[mt][nt][1] += c01.y;
            acc[mt][nt][2] += c23.x;
            acc[mt][nt][3] += c23.y;
        }

    // ---- epilogue: acc -> padded smem -> fully coalesced float4 stores ----
    __syncthreads();
    float* ebuf = (float*)(smem + OFF_TILES);
    #pragma unroll
    for (int mt = 0; mt < 2; mt++) {
        const int row = wm + mt * 16 + (lane >> 2);
        #pragma unroll
        for (int nt = 0; nt < 4; nt++) {
            const int col = wn + nt * 8 + (lane & 3) * 2;
            ebuf[row * EPS_ + col]           = acc[mt][nt][0];
            ebuf[row * EPS_ + col + 1]       = acc[mt][nt][1];
            ebuf[(row + 8) * EPS_ + col]     = acc[mt][nt][2];
            ebuf[(row + 8) * EPS_ + col + 1] = acc[mt][nt][3];
        }
    }
    __syncthreads();
    #pragma unroll
    for (int i = 0; i < 8; i++) {
        const int id  = tid + i * 512;      // 0..4095
        const int row = id >> 5;            // 0..127
        const int c4  = id & 31;            // float4 index in 128-col row
        float4 v = *(const float4*)&ebuf[row * EPS_ + c4 * 4];
        const float4 bb = *(const float4*)(g_bias3 + bn + c4 * 4);
        v.x += bb.x; v.y += bb.y; v.z += bb.z; v.w += bb.w;
        *(float4*)(g_tr + (size_t)(bm + row) * E3_ + bn + c4 * 4) = v;
    }
}

// ===========================================================================
// Scan: 128 blocks x 128 threads (single wave); 16-stage cp.async pipeline.
// ===========================================================================
#define SNS_ 16
#define SSTG_ 6144                       // 128 threads * 48 B
#define SCAN_SMEM (SNS_ * SSTG_)         // 98304

template<int PLEN, int WPF>
__device__ __forceinline__ void scan_body(int b, int n, int colbase,
                                          const int* __restrict__ input_len,
                                          const float* __restrict__ epsilon,
                                          float* __restrict__ out,
                                          char* ssm, uint32_t sb, int tidx) {
    float eps[PLEN - 1];
    #pragma unroll
    for (int i = 0; i < PLEN - 1; i++) eps[i] = epsilon[n * 5 + i];

    const int len = input_len[b];

    float h[PLEN];
    h[0] = 0.0f;
    #pragma unroll
    for (int i = 1; i < PLEN; i++) h[i] = ZERO_;
    float s = ZERO_;
    float ts = -1.0f;                   // tanhf(-100) == -1

    const float* base = g_tr + (size_t)b * E3_ + colbase;
    float* ob = out + (size_t)b * N_ + n;
    const size_t tstride = (size_t)B_ * E3_;
    const size_t ostride = (size_t)B_ * N_;
    const uint32_t slot = sb + tidx * 48;

    #pragma unroll
    for (int t = 0; t < SNS_ - 1; t++) {
        const float* g = base + (size_t)t * tstride;
        const uint32_t d = slot + t * SSTG_;
        if constexpr (WPF % 4 == 0) {
            #pragma unroll
            for (int q = 0; q < WPF / 4; q++) cpa16(d + q * 16, g + q * 4);
        } else {
            #pragma unroll
            for (int q = 0; q < WPF / 2; q++) cpa8(d + q * 8, g + q * 2);
        }
        CP_COMMIT();
    }

    #pragma unroll 4
    for (int t = 0; t < L_; t++) {
        CP_WAIT(SNS_ - 2);
        const uint32_t doff = (uint32_t)(tidx * 48) + (t & (SNS_ - 1)) * SSTG_;
        float q[2 * PLEN - 1];
        #pragma unroll
        for (int i = 0; i < 2 * PLEN - 1; i++)
            q[i] = *(const float*)(ssm + doff + i * 4);
        if (t + SNS_ - 1 < L_) {
            const float* g = base + (size_t)(t + SNS_ - 1) * tstride;
            const uint32_t nd = slot + ((t + SNS_ - 1) & (SNS_ - 1)) * SSTG_;
            if constexpr (WPF % 4 == 0) {
                #pragma unroll
                for (int qq = 0; qq < WPF / 4; qq++) cpa16(nd + qq * 16, g + qq * 4);
            } else {
                #pragma unroll
                for (int qq = 0; qq < WPF / 2; qq++) cpa8(nd + qq * 8, g + qq * 2);
            }
        }
        CP_COMMIT();

        float ae[PLEN];
        ae[0] = h[0];
        #pragma unroll
        for (int i = 1; i < PLEN; i++) ae[i] = fmaxf(h[i], h[i - 1] + eps[i - 1]);

        h[0] = fmaxf(0.0f, ae[0] + q[0]);
        #pragma unroll
        for (int i = 1; i < PLEN; i++)
            h[i] = fmaxf(ae[i - 1] + q[PLEN + i - 1], ae[i] + q[i]);

        float ev = h[PLEN - 1];
        if (len >= t && ev > s) {
            s = ev;
            ts = tanhf(s);
        }
        ob[(size_t)t * ostride] = ts;
    }
}

__global__ __launch_bounds__(128)
void sopa_scan(const int* __restrict__ input_len,
               const float* __restrict__ epsilon,
               float* __restrict__ out) {
    extern __shared__ char ssm[];
    const uint32_t sb = smem_to_u32(ssm);
    const int tidx = threadIdx.x;
    const int b    = blockIdx.x >> 1;
    const int half = blockIdx.x & 1;
    const int sub  = tidx >> 6;         // 0 or 1 within the half
    const int ln   = tidx & 63;         // pattern index within group
    const int g    = half * 2 + sub;    // group 0..3
    const int n    = (g << 6) | ln;

    switch (g) {
        case 0: scan_body<3, 6>(b, n, 0    + ln * 6,  input_len, epsilon, out, ssm, sb, tidx); break;
        case 1: scan_body<4, 8>(b, n, 384  + ln * 8,  input_len, epsilon, out, ssm, sb, tidx); break;
        case 2: scan_body<5, 10>(b, n, 896  + ln * 10, input_len, epsilon, out, ssm, sb, tidx); break;
        default: scan_body<6, 12>(b, n, 1536 + ln * 12, input_len, epsilon, out, ssm, sb, tidx); break;
    }
}

// ===========================================================================
extern "C" void kernel_launch(void* const* d_in, const int* in_sizes, int n_in,
                              void* d_out, int out_size) {
    const float* x         = (const float*)d_in[0];   // (L,B,D) f32
    const int*   input_len = (const int*)  d_in[1];   // (B,)   i32
    const float* diags     = (const float*)d_in[2];   // (E,D)  f32
    const float* bias      = (const float*)d_in[3];   // (E,1)  f32
    const float* epsilon   = (const float*)d_in[4];   // (N,P-1) f32
    float*       out       = (float*)d_out;           // (L,B,N) f32

    cudaFuncSetAttribute(sopa_gemm_mma, cudaFuncAttributeMaxDynamicSharedMemorySize,
                         SMEM_BYTES);
    cudaFuncSetAttribute(sopa_scan, cudaFuncAttributeMaxDynamicSharedMemorySize,
                         SCAN_SMEM);

    __half *xhi, *xlo;
    cudaGetSymbolAddress((void**)&xhi, g_xhi);
    cudaGetSymbolAddress((void**)&xlo, g_xlo);

    cvt_split_tiled<<<M_ * 32 / 256, 256>>>(x, xhi, xlo);   // 4096 blocks
    repack_w_tiled<<<E3_, 32>>>(diags, bias);

    dim3 ggrid(E3_ / 128, M_ / 128);   // (18, 256) — monolithic, 31.1 waves
    sopa_gemm_mma<<<ggrid, 512, SMEM_BYTES>>>();
    sopa_scan<<<128, 128, SCAN_SMEM>>>(input_len, epsilon, out);
}

// round 17
// speedup vs baseline: 1.1241x; 1.0195x over previous
#include <cuda_runtime.h>
#include <cuda_fp16.h>
#include <cstdint>

// Problem constants (Sopa_18897856102689)
#define L_ 512
#define B_ 64
#define D_ 256
#define N_ 256
#define P_ 6
#define M_ (L_ * B_)       // 32768
#define ZERO_ (-100.0f)

// FULLY PACKED transition columns: groups g=0..3 (plen=3..6, 64 patterns each)
// width w = 2*plen-1 = {5,7,9,11}; E2 = 64*(5+7+9+11) = 2048
// group bases {0, 320, 768, 1344}
#define E2_ 2048

// Scratch. x/W operands in TILE-IMAGE layout: one tile = (128 rows x 32
// halves) = 8192 contiguous bytes = one smem stage plane.
__device__ float  g_tr[(size_t)M_ * (size_t)E2_];               // 268.4 MB
__device__ __align__(128) __half g_xhi[(size_t)M_ * D_];        // 16.8 MB
__device__ __align__(128) __half g_xlo[(size_t)M_ * D_];
__device__ __align__(128) __half g_whi[(size_t)E2_ * D_];       // 1.05 MB
__device__ __align__(128) __half g_wlo[(size_t)E2_ * D_];
__device__ float  g_bias2[E2_];

// ===========================================================================
// helpers
// ===========================================================================
__device__ __forceinline__ uint32_t smem_to_u32(const void* p) {
    uint32_t a;
    asm("{ .reg .u64 t; cvta.to.shared.u64 t, %1; cvt.u32.u64 %0, t; }"
        : "=r"(a) : "l"(p));
    return a;
}
__device__ __forceinline__ void ldsm4(uint32_t* r, uint32_t addr) {
    asm volatile("ldmatrix.sync.aligned.m8n8.x4.shared.b16 {%0,%1,%2,%3}, [%4];"
        : "=r"(r[0]), "=r"(r[1]), "=r"(r[2]), "=r"(r[3]) : "r"(addr));
}
// fp32-accumulate HMMA (main term)
__device__ __forceinline__ void mma16816(float* d, const uint32_t* a,
                                         uint32_t b0, uint32_t b1) {
    asm volatile(
        "mma.sync.aligned.m16n8k16.row.col.f32.f16.f16.f32 "
        "{%0,%1,%2,%3}, {%4,%5,%6,%7}, {%8,%9}, {%0,%1,%2,%3};"
        : "+f"(d[0]), "+f"(d[1]), "+f"(d[2]), "+f"(d[3])
        : "r"(a[0]), "r"(a[1]), "r"(a[2]), "r"(a[3]), "r"(b0), "r"(b1));
}
// fp16-accumulate HMMA (small correction terms)
__device__ __forceinline__ void mma16816h(uint32_t* d, const uint32_t* a,
                                          uint32_t b0, uint32_t b1) {
    asm volatile(
        "mma.sync.aligned.m16n8k16.row.col.f16.f16.f16.f16 "
        "{%0,%1}, {%2,%3,%4,%5}, {%6,%7}, {%0,%1};"
        : "+r"(d[0]), "+r"(d[1])
        : "r"(a[0]), "r"(a[1]), "r"(a[2]), "r"(a[3]), "r"(b0), "r"(b1));
}
__device__ __forceinline__ uint32_t pack2(__half a, __half b) {
    __half2 t = __halves2half2(a, b);
    return *(uint32_t*)&t;
}
__device__ __forceinline__ void cpa4(uint32_t saddr, const void* gaddr) {
    asm volatile("cp.async.ca.shared.global [%0], [%1], 4;"
                 :: "r"(saddr), "l"(gaddr));
}
#define CP_COMMIT() asm volatile("cp.async.commit_group;" ::: "memory")
#define CP_WAIT(n)  asm volatile("cp.async.wait_group %0;" :: "n"(n) : "memory")

// bulk async copy global -> shared, mbarrier completion (sm_90 PTX)
__device__ __forceinline__ void bulk_g2s(uint32_t saddr, const void* gaddr,
                                         uint32_t bytes, uint32_t mbar) {
    asm volatile(
        "cp.async.bulk.shared::cluster.global.mbarrier::complete_tx::bytes "
        "[%0], [%1], %2, [%3];"
        :: "r"(saddr), "l"(gaddr), "r"(bytes), "r"(mbar) : "memory");
}
#define MBARRIER_INIT(mbar, cnt) \
    asm volatile("mbarrier.init.shared.b64 [%0], %1;" \
                 :: "r"((uint32_t)(mbar)), "r"((uint32_t)(cnt)) : "memory")
#define MBAR_EXPECT_TX(mbar, bytes) \
    asm volatile("mbarrier.arrive.expect_tx.shared.b64 _, [%0], %1;" \
                 :: "r"((uint32_t)(mbar)), "r"((uint32_t)(bytes)) : "memory")
#define MBARRIER_WAIT_PARITY(mbar, par) do {                                   \
    uint32_t _m = (uint32_t)(mbar);                                            \
    uint32_t _p = (uint32_t)(par);                                             \
    uint32_t _d;                                                               \
    asm volatile("{\n\t.reg .pred p;\n\t"                                      \
        "mbarrier.try_wait.parity.acquire.cta.shared::cta.b64 p, [%1], %2;\n\t"\
        "selp.b32 %0, 1, 0, p;\n\t}"                                           \
        : "=r"(_d) : "r"(_m), "r"(_p) : "memory");                             \
    if (!_d) {                                                                 \
        asm volatile("{\n\t.reg .pred P1;\n\t"                                 \
            "WAIT_LOOP_%=:\n\t"                                                \
            "mbarrier.try_wait.parity.acquire.cta.shared::cta.b64 P1, [%0], %1, 0x989680;\n\t" \
            "@P1 bra.uni WAIT_DONE_%=;\n\t"                                    \
            "bra.uni WAIT_LOOP_%=;\n\t"                                        \
            "WAIT_DONE_%=:\n\t}"                                               \
            :: "r"(_m), "r"(_p) : "memory");                                   \
    }                                                                          \
} while (0)

// swizzled byte offset within a 128x32-half tile image (row=64B, 16B granule)
__device__ __forceinline__ uint32_t swzc(int row, int chunk) {  // chunk 0..3
    return (uint32_t)(row * 64 + ((chunk ^ ((row >> 1) & 3)) << 4));
}

// ===========================================================================
// Convert x: fp32 -> (hi,lo) fp16 in TILE-IMAGE layout.
// ===========================================================================
__global__ __launch_bounds__(256)
void cvt_split_tiled(const float* __restrict__ src,
                     __half* __restrict__ hi_out, __half* __restrict__ lo_out) {
    const int i = blockIdx.x * 256 + threadIdx.x;
    const int m  = i >> 5;
    const int kq = i & 31;
    const float4 v0 = *(const float4*)(src + (size_t)m * D_ + kq * 8);
    const float4 v1 = *(const float4*)(src + (size_t)m * D_ + kq * 8 + 4);
    __half h0 = __float2half_rn(v0.x), h1 = __float2half_rn(v0.y);
    __half h2 = __float2half_rn(v0.z), h3 = __float2half_rn(v0.w);
    __half h4 = __float2half_rn(v1.x), h5 = __float2half_rn(v1.y);
    __half h6 = __float2half_rn(v1.z), h7 = __float2half_rn(v1.w);
    uint4 hi = { pack2(h0, h1), pack2(h2, h3), pack2(h4, h5), pack2(h6, h7) };
    uint4 lo = { pack2(__float2half_rn(v0.x - __half2float(h0)),
                       __float2half_rn(v0.y - __half2float(h1))),
                 pack2(__float2half_rn(v0.z - __half2float(h2)),
                       __float2half_rn(v0.w - __half2float(h3))),
                 pack2(__float2half_rn(v1.x - __half2float(h4)),
                       __float2half_rn(v1.y - __half2float(h5))),
                 pack2(__float2half_rn(v1.z - __half2float(h6)),
                       __float2half_rn(v1.w - __half2float(h7))) };
    const size_t off = (size_t)((m >> 7) * 8 + (kq >> 2)) * 8192
                     + swzc(m & 127, kq & 3);
    *(uint4*)((char*)hi_out + off) = hi;
    *(uint4*)((char*)lo_out + off) = lo;
}

// ===========================================================================
// Repack W into packed rows (E2) in TILE-IMAGE layout + bias gather.
// Column j within a pattern row (width w): [self p=0..plen-1, adv p=0..plen-2]
// ===========================================================================
__global__ __launch_bounds__(32)
void repack_w_tiled(const float* __restrict__ diags, const float* __restrict__ bias) {
    const int e2 = blockIdx.x;
    int g, base;
    if (e2 < 320)       { g = 0; base = 0; }
    else if (e2 < 768)  { g = 1; base = 320; }
    else if (e2 < 1344) { g = 2; base = 768; }
    else                { g = 3; base = 1344; }
    const int plen = g + 3;
    const int w = 2 * plen - 1;
    const int r0 = e2 - base;
    const int nl = r0 / w;
    const int j = r0 - nl * w;
    const int n = (g << 6) + nl;
    const int e_orig = n * 12 + (j < plen ? j : 6 + (j - plen));

    const int t = threadIdx.x;                      // 0..31 (8-half chunks)
    const float4 v0 = *(const float4*)(diags + (size_t)e_orig * D_ + t * 8);
    const float4 v1 = *(const float4*)(diags + (size_t)e_orig * D_ + t * 8 + 4);
    __half h0 = __float2half_rn(v0.x), h1 = __float2half_rn(v0.y);
    __half h2 = __float2half_rn(v0.z), h3 = __float2half_rn(v0.w);
    __half h4 = __float2half_rn(v1.x), h5 = __float2half_rn(v1.y);
    __half h6 = __float2half_rn(v1.z), h7 = __float2half_rn(v1.w);
    uint4 hi = make_uint4(pack2(h0, h1), pack2(h2, h3), pack2(h4, h5), pack2(h6, h7));
    uint4 lo = make_uint4(pack2(__float2half_rn(v0.x - __half2float(h0)),
                                __float2half_rn(v0.y - __half2float(h1))),
                          pack2(__float2half_rn(v0.z - __half2float(h2)),
                                __float2half_rn(v0.w - __half2float(h3))),
                          pack2(__float2half_rn(v1.x - __half2float(h4)),
                                __float2half_rn(v1.y - __half2float(h5))),
                          pack2(__float2half_rn(v1.z - __half2float(h6)),
                                __float2half_rn(v1.w - __half2float(h7))));
    const size_t off = (size_t)((e2 >> 7) * 8 + (t >> 2)) * 8192
                     + swzc(e2 & 127, t & 3);
    *(uint4*)((char*)g_whi + off) = hi;
    *(uint4*)((char*)g_wlo + off) = lo;
    if (t == 0) g_bias2[e2] = bias[e_orig];
}

// ===========================================================================
// GEMM: C[m][e2] = sum_k x[m][k]*Wpacked[e2][k] + bias2[e2]
// hi*hi fp32-acc; hi*lo + lo*hi fp16-acc (merged at epilogue).
// Bulk staging; coalesced smem epilogue. BM=128, BN=128, BK=32, 512 thr.
// ===========================================================================
#define NCHUNK_ 8
#define NSTAGE_ 4
#define ST_AHI 0
#define ST_ALO 8192
#define ST_BHI 16384
#define ST_BLO 24576
#define STAGE_SZ 32768
#define OFF_MBAR  512
#define OFF_TILES 1024
#define SMEM_BYTES (OFF_TILES + NSTAGE_ * STAGE_SZ)   // 132096
#define EPS_ 136   // epilogue smem row stride (floats)

__device__ __forceinline__ void gemm_issue_bulk(uint32_t sb, int slot,
                                                int chunk, int mb, int nb) {
    const uint32_t stg = sb + OFF_TILES + slot * STAGE_SZ;
    const uint32_t mbar = sb + OFF_MBAR + slot * 8;
    MBAR_EXPECT_TX(mbar, 4 * 8192);
    const size_t at = (size_t)(mb * 8 + chunk) * 8192;
    const size_t bt = (size_t)(nb * 8 + chunk) * 8192;
    bulk_g2s(stg + ST_AHI, (const char*)g_xhi + at, 8192, mbar);
    bulk_g2s(stg + ST_ALO, (const char*)g_xlo + at, 8192, mbar);
    bulk_g2s(stg + ST_BHI, (const char*)g_whi + bt, 8192, mbar);
    bulk_g2s(stg + ST_BLO, (const char*)g_wlo + bt, 8192, mbar);
}

__global__ __launch_bounds__(512, 1)
void sopa_gemm_mma() {
    extern __shared__ char smem[];
    const uint32_t sb = smem_to_u32(smem);
    const int tid  = threadIdx.x;
    const int lane = tid & 31;
    const int warp = tid >> 5;
    const int wm = (warp >> 2) * 32;
    const int wn = (warp & 3) * 32;

    const int nb = blockIdx.x;          // e2 block (0..15)
    const int mb = blockIdx.y;          // m block (0..255)
    const int bn = nb * 128;
    const int bm = mb * 128;

    if (tid == 0) {
        #pragma unroll
        for (int s = 0; s < NSTAGE_; s++)
            MBARRIER_INIT(sb + OFF_MBAR + s * 8, 1);
    }
    __syncthreads();

    if (tid == 0) {
        #pragma unroll
        for (int s = 0; s < NSTAGE_ - 1; s++)
            gemm_issue_bulk(sb, s, s, mb, nb);
    }

    float acc[2][4][4];
    uint32_t accC[2][4][2];             // fp16 correction accumulators
    #pragma unroll
    for (int i = 0; i < 2; i++)
        #pragma unroll
        for (int j = 0; j < 4; j++) {
            #pragma unroll
            for (int k = 0; k < 4; k++) acc[i][j][k] = 0.0f;
            accC[i][j][0] = 0u;
            accC[i][j][1] = 0u;
        }

    const int lrow = lane & 15;
    const int lsel = lane >> 4;

    #pragma unroll
    for (int c = 0; c < NCHUNK_; c++) {
        MBARRIER_WAIT_PARITY(sb + OFF_MBAR + (c & 3) * 8, (c >> 2) & 1);
        __syncthreads();
        if (tid == 0 && c + NSTAGE_ - 1 < NCHUNK_)
            gemm_issue_bulk(sb, (c + NSTAGE_ - 1) & 3, c + NSTAGE_ - 1, mb, nb);

        const uint32_t st = sb + OFF_TILES + (c & 3) * STAGE_SZ;
        #pragma unroll
        for (int kk = 0; kk < 2; kk++) {
            const int chunk = kk * 2 + lsel;
            uint32_t aHi[2][4], aLo[2][4], bHi[2][4], bLo[2][4];
            #pragma unroll
            for (int mt = 0; mt < 2; mt++) {
                const uint32_t off = swzc(wm + mt * 16 + lrow, chunk);
                ldsm4(aHi[mt], st + ST_AHI + off);
                ldsm4(aLo[mt], st + ST_ALO + off);
            }
            #pragma unroll
            for (int ng = 0; ng < 2; ng++) {
                const uint32_t off = swzc(wn + ng * 16 + lrow, chunk);
                ldsm4(bHi[ng], st + ST_BHI + off);
                ldsm4(bLo[ng], st + ST_BLO + off);
            }
            #pragma unroll
            for (int mt = 0; mt < 2; mt++)
                #pragma unroll
                for (int nt = 0; nt < 4; nt++) {
                    const int ng = nt >> 1, sl = nt & 1;
                    mma16816(acc[mt][nt], aHi[mt], bHi[ng][sl], bHi[ng][sl + 2]);
                    mma16816h(accC[mt][nt], aHi[mt], bLo[ng][sl], bLo[ng][sl + 2]);
                    mma16816h(accC[mt][nt], aLo[mt], bHi[ng][sl], bHi[ng][sl + 2]);
                }
        }
    }

    // merge fp16 corrections into fp32 accumulators
    #pragma unroll
    for (int mt = 0; mt < 2; mt++)
        #pragma unroll
        for (int nt = 0; nt < 4; nt++) {
            float2 c01 = __half22float2(*(__half2*)&accC[mt][nt][0]);
            float2 c23 = __half22float2(*(__half2*)&accC[mt][nt][1]);
            acc[mt][nt][0] += c01.x;
            acc[mt][nt][1] += c01.y;
            acc[mt][nt][2] += c23.x;
            acc[mt][nt][3] += c23.y;
        }

    // ---- epilogue: acc -> padded smem -> fully coalesced float4 stores ----
    __syncthreads();
    float* ebuf = (float*)(smem + OFF_TILES);
    #pragma unroll
    for (int mt = 0; mt < 2; mt++) {
        const int row = wm + mt * 16 + (lane >> 2);
        #pragma unroll
        for (int nt = 0; nt < 4; nt++) {
            const int col = wn + nt * 8 + (lane & 3) * 2;
            ebuf[row * EPS_ + col]           = acc[mt][nt][0];
            ebuf[row * EPS_ + col + 1]       = acc[mt][nt][1];
            ebuf[(row + 8) * EPS_ + col]     = acc[mt][nt][2];
            ebuf[(row + 8) * EPS_ + col + 1] = acc[mt][nt][3];
        }
    }
    __syncthreads();
    #pragma unroll
    for (int i = 0; i < 8; i++) {
        const int id  = tid + i * 512;      // 0..4095
        const int row = id >> 5;            // 0..127
        const int c4  = id & 31;            // float4 index in 128-col row
        float4 v = *(const float4*)&ebuf[row * EPS_ + c4 * 4];
        const float4 bb = *(const float4*)(g_bias2 + bn + c4 * 4);
        v.x += bb.x; v.y += bb.y; v.z += bb.z; v.w += bb.w;
        *(float4*)(g_tr + (size_t)(bm + row) * E2_ + bn + c4 * 4) = v;
    }
}

// ===========================================================================
// Scan: 128 blocks x 128 threads (single wave); 16-stage cp.async pipeline.
// Packed layout: row width w = 2*PLEN-1 floats; 4B cp.async per float
// (addresses 4B-aligned; consecutive threads' rows tile contiguously).
// ===========================================================================
#define SNS_ 16
#define SSTG_ 6144                       // 128 threads * 48 B
#define SCAN_SMEM (SNS_ * SSTG_)         // 98304

template<int PLEN>
__device__ __forceinline__ void scan_body(int b, int n, int colbase,
                                          const int* __restrict__ input_len,
                                          const float* __restrict__ epsilon,
                                          float* __restrict__ out,
                                          char* ssm, uint32_t sb, int tidx) {
    constexpr int W = 2 * PLEN - 1;
    float eps[PLEN - 1];
    #pragma unroll
    for (int i = 0; i < PLEN - 1; i++) eps[i] = epsilon[n * 5 + i];

    const int len = input_len[b];

    float h[PLEN];
    h[0] = 0.0f;
    #pragma unroll
    for (int i = 1; i < PLEN; i++) h[i] = ZERO_;
    float s = ZERO_;
    float ts = -1.0f;                   // tanhf(-100) == -1

    const float* base = g_tr + (size_t)b * E2_ + colbase;
    float* ob = out + (size_t)b * N_ + n;
    const size_t tstride = (size_t)B_ * E2_;
    const size_t ostride = (size_t)B_ * N_;
    const uint32_t slot = sb + tidx * 48;

    #pragma unroll
    for (int t = 0; t < SNS_ - 1; t++) {
        const float* g = base + (size_t)t * tstride;
        const uint32_t d = slot + t * SSTG_;
        #pragma unroll
        for (int q = 0; q < W; q++) cpa4(d + q * 4, g + q);
        CP_COMMIT();
    }

    #pragma unroll 4
    for (int t = 0; t < L_; t++) {
        CP_WAIT(SNS_ - 2);
        const uint32_t doff = (uint32_t)(tidx * 48) + (t & (SNS_ - 1)) * SSTG_;
        float q[W];
        #pragma unroll
        for (int i = 0; i < W; i++)
            q[i] = *(const float*)(ssm + doff + i * 4);
        if (t + SNS_ - 1 < L_) {
            const float* g = base + (size_t)(t + SNS_ - 1) * tstride;
            const uint32_t nd = slot + ((t + SNS_ - 1) & (SNS_ - 1)) * SSTG_;
            #pragma unroll
            for (int qq = 0; qq < W; qq++) cpa4(nd + qq * 4, g + qq);
        }
        CP_COMMIT();

        float ae[PLEN];
        ae[0] = h[0];
        #pragma unroll
        for (int i = 1; i < PLEN; i++) ae[i] = fmaxf(h[i], h[i - 1] + eps[i - 1]);

        h[0] = fmaxf(0.0f, ae[0] + q[0]);
        #pragma unroll
        for (int i = 1; i < PLEN; i++)
            h[i] = fmaxf(ae[i - 1] + q[PLEN + i - 1], ae[i] + q[i]);

        float ev = h[PLEN - 1];
        if (len >= t && ev > s) {
            s = ev;
            ts = tanhf(s);
        }
        ob[(size_t)t * ostride] = ts;
    }
}

__global__ __launch_bounds__(128)
void sopa_scan(const int* __restrict__ input_len,
               const float* __restrict__ epsilon,
               float* __restrict__ out) {
    extern __shared__ char ssm[];
    const uint32_t sb = smem_to_u32(ssm);
    const int tidx = threadIdx.x;
    const int b    = blockIdx.x >> 1;
    const int half = blockIdx.x & 1;
    const int sub  = tidx >> 6;         // 0 or 1 within the half
    const int ln   = tidx & 63;         // pattern index within group
    const int g    = half * 2 + sub;    // group 0..3
    const int n    = (g << 6) | ln;

    switch (g) {
        case 0: scan_body<3>(b, n, 0    + ln * 5,  input_len, epsilon, out, ssm, sb, tidx); break;
        case 1: scan_body<4>(b, n, 320  + ln * 7,  input_len, epsilon, out, ssm, sb, tidx); break;
        case 2: scan_body<5>(b, n, 768  + ln * 9,  input_len, epsilon, out, ssm, sb, tidx); break;
        default: scan_body<6>(b, n, 1344 + ln * 11, input_len, epsilon, out, ssm, sb, tidx); break;
    }
}

// ===========================================================================
extern "C" void kernel_launch(void* const* d_in, const int* in_sizes, int n_in,
                              void* d_out, int out_size) {
    const float* x         = (const float*)d_in[0];   // (L,B,D) f32
    const int*   input_len = (const int*)  d_in[1];   // (B,)   i32
    const float* diags     = (const float*)d_in[2];   // (E,D)  f32
    const float* bias      = (const float*)d_in[3];   // (E,1)  f32
    const float* epsilon   = (const float*)d_in[4];   // (N,P-1) f32
    float*       out       = (float*)d_out;           // (L,B,N) f32

    cudaFuncSetAttribute(sopa_gemm_mma, cudaFuncAttributeMaxDynamicSharedMemorySize,
                         SMEM_BYTES);
    cudaFuncSetAttribute(sopa_scan, cudaFuncAttributeMaxDynamicSharedMemorySize,
                         SCAN_SMEM);

    __half *xhi, *xlo;
    cudaGetSymbolAddress((void**)&xhi, g_xhi);
    cudaGetSymbolAddress((void**)&xlo, g_xlo);

    cvt_split_tiled<<<M_ * 32 / 256, 256>>>(x, xhi, xlo);   // 4096 blocks
    repack_w_tiled<<<E2_, 32>>>(diags, bias);

    dim3 ggrid(E2_ / 128, M_ / 128);   // (16, 256) — monolithic
    sopa_gemm_mma<<<ggrid, 512, SMEM_BYTES>>>();
    sopa_scan<<<128, 128, SCAN_SMEM>>>(input_len, epsilon, out);
}